// round 2
// baseline (speedup 1.0000x reference)
#include <cuda_runtime.h>
#include <cstdint>

// ============================================================
// SVDDecomposeTransMatrix:
//   m_left  = Cayley(u_left)  @ diag(diag_left)  @ Cayley(v_left)    [64x64]
//   m_right = Cayley(u_right) @ diag(diag_right) @ Cayley(v_right)   [64x64]
//   xs = x * diag_scale ; per 64x64 tile: out = m_left^T @ Xs @ m_right
// ============================================================

__device__ float g_Q[4][64 * 64];
__device__ float g_ML[64 * 64];   // TRANSPOSED m_left: g_ML[l*64+i] = m_left[i][l]
__device__ float g_MR[64 * 64];   // m_right, row-major

// ---------------- Prep 1: Cayley via Gauss-Jordan (4 blocks) ----------------
// Q = (I - A/2)^{-1} (I + A/2),  A = tril(X,-1) - tril(X,-1)^T
__global__ void cayley_kernel(const float* __restrict__ u_left,
                              const float* __restrict__ v_left,
                              const float* __restrict__ u_right,
                              const float* __restrict__ v_right) {
    __shared__ float sB[64][65];
    __shared__ float sC[64][65];
    const float* X = (blockIdx.x == 0) ? u_left :
                     (blockIdx.x == 1) ? v_left :
                     (blockIdx.x == 2) ? u_right : v_right;
    int tid = threadIdx.x;  // 256 threads

    for (int idx = tid; idx < 4096; idx += 256) {
        int i = idx >> 6, j = idx & 63;
        float a = (i > j) ? X[i * 64 + j] : (i < j ? -X[j * 64 + i] : 0.f);
        float e = (i == j) ? 1.f : 0.f;
        sB[i][j] = e - 0.5f * a;
        sC[i][j] = e + 0.5f * a;
    }
    __syncthreads();

    // Gauss-Jordan, no pivoting (B ~= I, extremely well conditioned)
    for (int p = 0; p < 64; ++p) {
        float inv = 1.0f / sB[p][p];   // broadcast read by all threads
        __syncthreads();               // readers done before row-p scaling writes
        if (tid < 64)        sB[p][tid] *= inv;
        else if (tid < 128)  sC[p][tid - 64] *= inv;
        __syncthreads();               // row p scaled before elimination reads it
        int half = tid >> 7;           // 0/1
        int c = tid & 127;             // 0..63 -> B col, 64..127 -> C col
        for (int rr = 0; rr < 64; rr += 2) {
            int r = rr + half;
            if (r != p) {
                float f = sB[r][p];    // nobody writes col p (skipped below) -> no race
                if (c < 64) { if (c != p) sB[r][c] -= f * sB[p][c]; }
                else        sC[r][c - 64] -= f * sC[p][c - 64];
            }
        }
        __syncthreads();
    }

    float* dst = g_Q[blockIdx.x];
    for (int idx = tid; idx < 4096; idx += 256) {
        int i = idx >> 6, j = idx & 63;
        dst[idx] = sC[i][j];
    }
}

// ---------------- Prep 2: compose M = Qa @ diag(d) @ Qb (2 blocks) ----------------
__global__ void compose_kernel(const float* __restrict__ diag_left,
                               const float* __restrict__ diag_right) {
    __shared__ float sA[64][65];  // Qa
    __shared__ float sD[64][65];  // d[c] * Qb[c][b]
    int tid = threadIdx.x;  // 256
    const float* Qa = g_Q[blockIdx.x * 2];
    const float* Qb = g_Q[blockIdx.x * 2 + 1];
    const float* d  = blockIdx.x ? diag_right : diag_left;

    for (int idx = tid; idx < 4096; idx += 256) {
        int i = idx >> 6, j = idx & 63;
        sA[i][j] = Qa[idx];
        sD[i][j] = d[i] * Qb[idx];
    }
    __syncthreads();

    for (int idx = tid; idx < 4096; idx += 256) {
        int a = idx >> 6, b = idx & 63;
        float acc = 0.f;
#pragma unroll 8
        for (int c = 0; c < 64; ++c) acc += sA[a][c] * sD[c][b];
        if (blockIdx.x == 0) g_ML[b * 64 + a] = acc;   // store m_left TRANSPOSED
        else                 g_MR[a * 64 + b] = acc;
    }
}

// ---------------- Main: persistent batched 64x64x64x2 GEMM, TF32 mma ----------------
#define SSTR 72   // smem row stride in floats (conflict-free B-fragment reads)

__device__ __forceinline__ unsigned f2tf(float f) {
    unsigned u;
    asm("cvt.rna.tf32.f32 %0, %1;" : "=r"(u) : "f"(f));
    return u;
}

__device__ __forceinline__ void mma_tf32(float& d0, float& d1, float& d2, float& d3,
                                         unsigned a0, unsigned a1, unsigned a2, unsigned a3,
                                         unsigned b0, unsigned b1) {
    asm volatile(
        "mma.sync.aligned.m16n8k8.row.col.f32.tf32.tf32.f32 "
        "{%0,%1,%2,%3}, {%4,%5,%6,%7}, {%8,%9}, {%0,%1,%2,%3};\n"
        : "+f"(d0), "+f"(d1), "+f"(d2), "+f"(d3)
        : "r"(a0), "r"(a1), "r"(a2), "r"(a3), "r"(b0), "r"(b1));
}

__global__ __launch_bounds__(128)
void kron_kernel(const float* __restrict__ x,
                 const float* __restrict__ diag_scale,
                 float* __restrict__ out, int ntiles) {
    extern __shared__ float smem[];
    float* sDiag = smem;                       // 4096 floats (fp32, applied at load)
    float* sMR   = smem + 4096;                // 64*SSTR (tf32 bits)
    float* sXs   = sMR + 64 * SSTR;            // 64*SSTR (tf32 bits)
    float* sT    = sXs + 64 * SSTR;            // 4 warps * 16*SSTR (tf32 bits)

    int tid  = threadIdx.x;
    int warp = tid >> 5, lane = tid & 31;
    int g = lane >> 2, t4 = lane & 3;
    int strip = warp * 16;                     // this warp's 16 output rows (l)

    // ---- one-time per-CTA init: diag + M_R to smem, M_L^T A-fragments to regs ----
    for (int i = tid; i < 4096; i += 128) {
        sDiag[i] = diag_scale[i];
        int r = i >> 6, c = i & 63;
        sMR[r * SSTR + c] = __uint_as_float(f2tf(g_MR[i]));
    }
    unsigned a1f[8][4];
#pragma unroll
    for (int kk = 0; kk < 8; ++kk) {
        int i0 = kk * 8 + t4;
        a1f[kk][0] = f2tf(g_ML[(strip + g)     * 64 + i0]);
        a1f[kk][1] = f2tf(g_ML[(strip + g + 8) * 64 + i0]);
        a1f[kk][2] = f2tf(g_ML[(strip + g)     * 64 + i0 + 4]);
        a1f[kk][3] = f2tf(g_ML[(strip + g + 8) * 64 + i0 + 4]);
    }
    __syncthreads();
    float* sTw = sT + warp * 16 * SSTR;

    for (int t = blockIdx.x; t < ntiles; t += gridDim.x) {
        // ---- stage Xs = x_tile * diag_scale into smem (tf32 bits, stride-72 rows) ----
        const float4* xt = (const float4*)(x + (size_t)t * 4096);
        const float4* dg = (const float4*)sDiag;
#pragma unroll
        for (int it = 0; it < 8; ++it) {
            int idx = it * 128 + tid;              // float4 index 0..1023
            float4 v = xt[idx];
            float4 s = dg[idx];
            uint4 pk = make_uint4(f2tf(v.x * s.x), f2tf(v.y * s.y),
                                  f2tf(v.z * s.z), f2tf(v.w * s.w));
            int row = idx >> 4, col = (idx & 15) << 2;
            *(uint4*)&sXs[row * SSTR + col] = pk;
        }
        __syncthreads();

        // ---- GEMM1: T_strip[16 x 64] = (M_L^T)_strip @ Xs  (k = i) ----
#pragma unroll
        for (int nn = 0; nn < 8; ++nn) {
            float c0 = 0.f, c1 = 0.f, c2 = 0.f, c3 = 0.f;
#pragma unroll
            for (int kk = 0; kk < 8; ++kk) {
                unsigned b0 = __float_as_uint(sXs[(kk * 8 + t4)     * SSTR + nn * 8 + g]);
                unsigned b1 = __float_as_uint(sXs[(kk * 8 + t4 + 4) * SSTR + nn * 8 + g]);
                mma_tf32(c0, c1, c2, c3,
                         a1f[kk][0], a1f[kk][1], a1f[kk][2], a1f[kk][3], b0, b1);
            }
            // stage to warp-private strip (tf32 bits), C-layout -> row-major
            *(uint2*)&sTw[g       * SSTR + nn * 8 + 2 * t4] = make_uint2(f2tf(c0), f2tf(c1));
            *(uint2*)&sTw[(g + 8) * SSTR + nn * 8 + 2 * t4] = make_uint2(f2tf(c2), f2tf(c3));
        }
        __syncwarp();   // warp-local: T written by this warp, read only by this warp

        // ---- A2 fragments from T_strip (k = j) ----
        unsigned a2f[8][4];
#pragma unroll
        for (int kk = 0; kk < 8; ++kk) {
            int j0 = kk * 8 + t4;
            a2f[kk][0] = __float_as_uint(sTw[g       * SSTR + j0]);
            a2f[kk][1] = __float_as_uint(sTw[(g + 8) * SSTR + j0]);
            a2f[kk][2] = __float_as_uint(sTw[g       * SSTR + j0 + 4]);
            a2f[kk][3] = __float_as_uint(sTw[(g + 8) * SSTR + j0 + 4]);
        }

        // ---- GEMM2: O_strip = T_strip @ M_R, direct coalesced store ----
        float* ot = out + (size_t)t * 4096;
#pragma unroll
        for (int nn = 0; nn < 8; ++nn) {
            float c0 = 0.f, c1 = 0.f, c2 = 0.f, c3 = 0.f;
#pragma unroll
            for (int kk = 0; kk < 8; ++kk) {
                unsigned b0 = __float_as_uint(sMR[(kk * 8 + t4)     * SSTR + nn * 8 + g]);
                unsigned b1 = __float_as_uint(sMR[(kk * 8 + t4 + 4) * SSTR + nn * 8 + g]);
                mma_tf32(c0, c1, c2, c3,
                         a2f[kk][0], a2f[kk][1], a2f[kk][2], a2f[kk][3], b0, b1);
            }
            int row = strip + g, col = nn * 8 + 2 * t4;
            *(float2*)&ot[row * 64 + col]       = make_float2(c0, c1);
            *(float2*)&ot[(row + 8) * 64 + col] = make_float2(c2, c3);
        }
        __syncthreads();   // all warps done with sXs before next tile overwrites it
    }
}

// ---------------- launch ----------------
extern "C" void kernel_launch(void* const* d_in, const int* in_sizes, int n_in,
                              void* d_out, int out_size) {
    const float* x          = (const float*)d_in[0];
    const float* u_left     = (const float*)d_in[1];
    const float* v_left     = (const float*)d_in[2];
    const float* diag_left  = (const float*)d_in[3];
    const float* u_right    = (const float*)d_in[4];
    const float* v_right    = (const float*)d_in[5];
    const float* diag_right = (const float*)d_in[6];
    const float* diag_scale = (const float*)d_in[7];
    float* out = (float*)d_out;

    int ntiles = in_sizes[0] / 4096;

    cayley_kernel<<<4, 256>>>(u_left, v_left, u_right, v_right);
    compose_kernel<<<2, 256>>>(diag_left, diag_right);

    const int SMEM_BYTES = (4096 + 3 * 64 * SSTR) * (int)sizeof(float);  // 71680
    cudaFuncSetAttribute(kron_kernel, cudaFuncAttributeMaxDynamicSharedMemorySize, SMEM_BYTES);
    int grid = ntiles < 456 ? (ntiles > 0 ? ntiles : 1) : 456;  // 152 SMs * 3
    kron_kernel<<<grid, 128, SMEM_BYTES>>>(x, diag_scale, out, ntiles);
}

// round 3
// speedup vs baseline: 1.9683x; 1.9683x over previous
#include <cuda_runtime.h>
#include <cstdint>

// ============================================================
// SVDDecomposeTransMatrix:
//   m_left  = Cayley(u_left)  @ diag(diag_left)  @ Cayley(v_left)    [64x64]
//   m_right = Cayley(u_right) @ diag(diag_right) @ Cayley(v_right)   [64x64]
//   xs = x * diag_scale ; per 64x64 tile: out = m_left^T @ Xs @ m_right
//
// Cayley via truncated geometric series with doubling (||A/2|| ~ 0.16):
//   (I-B)^{-1} = sum B^k ; S<-S+P*S, P<-P*P ; Q = (I+B)*S
// ============================================================

__device__ float g_Q[4][64 * 64];
__device__ float g_ML[64 * 64];   // TRANSPOSED m_left: g_ML[l*64+i] = m_left[i][l]
__device__ float g_MR[64 * 64];   // m_right, row-major

#define MSTR 68   // smem row stride (floats) for prep matmuls: float4-aligned, conflict-free

// C = A*B, 64x64, all smem arrays stride MSTR, 256 threads, 4x4 register tiles.
__device__ __forceinline__ void mm64(const float* __restrict__ A,
                                     const float* __restrict__ B,
                                     float* __restrict__ C, int tid) {
    int c0 = (tid & 15) * 4;
    int r0 = (tid >> 4) * 4;
    float acc00=0,acc01=0,acc02=0,acc03=0, acc10=0,acc11=0,acc12=0,acc13=0;
    float acc20=0,acc21=0,acc22=0,acc23=0, acc30=0,acc31=0,acc32=0,acc33=0;
#pragma unroll 8
    for (int k = 0; k < 64; ++k) {
        float4 b = *(const float4*)&B[k * MSTR + c0];
        float a0 = A[(r0 + 0) * MSTR + k];
        float a1 = A[(r0 + 1) * MSTR + k];
        float a2 = A[(r0 + 2) * MSTR + k];
        float a3 = A[(r0 + 3) * MSTR + k];
        acc00 += a0*b.x; acc01 += a0*b.y; acc02 += a0*b.z; acc03 += a0*b.w;
        acc10 += a1*b.x; acc11 += a1*b.y; acc12 += a1*b.z; acc13 += a1*b.w;
        acc20 += a2*b.x; acc21 += a2*b.y; acc22 += a2*b.z; acc23 += a2*b.w;
        acc30 += a3*b.x; acc31 += a3*b.y; acc32 += a3*b.z; acc33 += a3*b.w;
    }
    *(float4*)&C[(r0 + 0) * MSTR + c0] = make_float4(acc00, acc01, acc02, acc03);
    *(float4*)&C[(r0 + 1) * MSTR + c0] = make_float4(acc10, acc11, acc12, acc13);
    *(float4*)&C[(r0 + 2) * MSTR + c0] = make_float4(acc20, acc21, acc22, acc23);
    *(float4*)&C[(r0 + 3) * MSTR + c0] = make_float4(acc30, acc31, acc32, acc33);
}

__device__ __forceinline__ void add64(float* __restrict__ S,
                                      const float* __restrict__ T, int tid) {
    for (int idx = tid; idx < 4096; idx += 256) {
        int i = idx >> 6, j = idx & 63;
        S[i * MSTR + j] += T[i * MSTR + j];
    }
}

// ---------------- Prep 1: 4 Cayley transforms (one per block) ----------------
__global__ __launch_bounds__(256)
void cayley_kernel(const float* __restrict__ u_left,
                   const float* __restrict__ v_left,
                   const float* __restrict__ u_right,
                   const float* __restrict__ v_right) {
    extern __shared__ float sm[];
    float* sB = sm;                    // B = A/2
    float* sS = sB + 64 * MSTR;        // series accumulator
    float* bufP = sS + 64 * MSTR;
    float* bufT = bufP + 64 * MSTR;

    const float* X = (blockIdx.x == 0) ? u_left :
                     (blockIdx.x == 1) ? v_left :
                     (blockIdx.x == 2) ? u_right : v_right;
    int tid = threadIdx.x;

    for (int idx = tid; idx < 4096; idx += 256) {
        int i = idx >> 6, j = idx & 63;
        float a = (i > j) ? X[i * 64 + j] : (i < j ? -X[j * 64 + i] : 0.f);
        float b = 0.5f * a;
        sB[i * MSTR + j] = b;
        sS[i * MSTR + j] = (i == j) ? 1.f + b : b;   // S = I + B  (terms k<2)
    }
    __syncthreads();

    float *P = bufP, *T = bufT, *tmp;
    mm64(sB, sB, P, tid); __syncthreads();                     // P = B^2
    mm64(P, sS, T, tid);  __syncthreads(); add64(sS, T, tid); __syncthreads(); // S: k<4
    mm64(P, P, T, tid);   __syncthreads(); tmp=P; P=T; T=tmp;  // P = B^4
    mm64(P, sS, T, tid);  __syncthreads(); add64(sS, T, tid); __syncthreads(); // S: k<8
    mm64(P, P, T, tid);   __syncthreads(); tmp=P; P=T; T=tmp;  // P = B^8
    mm64(P, sS, T, tid);  __syncthreads(); add64(sS, T, tid); __syncthreads(); // S: k<16
    mm64(P, P, T, tid);   __syncthreads(); tmp=P; P=T; T=tmp;  // P = B^16
    mm64(P, sS, T, tid);  __syncthreads(); add64(sS, T, tid); __syncthreads(); // S: k<32
    mm64(sB, sS, T, tid); __syncthreads(); add64(sS, T, tid); __syncthreads(); // Q=(I+B)S

    float* dst = g_Q[blockIdx.x];
    for (int idx = tid; idx < 4096; idx += 256) {
        int i = idx >> 6, j = idx & 63;
        dst[idx] = sS[i * MSTR + j];
    }
}

// ---------------- Prep 2: compose M = Qa @ diag(d) @ Qb (2 blocks) ----------------
__global__ __launch_bounds__(256)
void compose_kernel(const float* __restrict__ diag_left,
                    const float* __restrict__ diag_right) {
    extern __shared__ float sm[];
    float* sA = sm;                   // Qa
    float* sD = sA + 64 * MSTR;       // d[c] * Qb[c][b]
    float* sC = sD + 64 * MSTR;
    int tid = threadIdx.x;
    const float* Qa = g_Q[blockIdx.x * 2];
    const float* Qb = g_Q[blockIdx.x * 2 + 1];
    const float* d  = blockIdx.x ? diag_right : diag_left;

    for (int idx = tid; idx < 4096; idx += 256) {
        int i = idx >> 6, j = idx & 63;
        sA[i * MSTR + j] = Qa[idx];
        sD[i * MSTR + j] = d[i] * Qb[idx];
    }
    __syncthreads();
    mm64(sA, sD, sC, tid);
    __syncthreads();
    for (int idx = tid; idx < 4096; idx += 256) {
        int a = idx >> 6, b = idx & 63;
        float v = sC[a * MSTR + b];
        if (blockIdx.x == 0) g_ML[b * 64 + a] = v;   // store m_left TRANSPOSED
        else                 g_MR[a * 64 + b] = v;
    }
}

// ---------------- Main: persistent batched 64x64x64x2 GEMM, TF32 mma ----------------
#define SSTR 72   // smem row stride in floats (conflict-free B-fragment reads)

__device__ __forceinline__ unsigned f2tf(float f) {
    unsigned u;
    asm("cvt.rna.tf32.f32 %0, %1;" : "=r"(u) : "f"(f));
    return u;
}

__device__ __forceinline__ void mma_tf32(float& d0, float& d1, float& d2, float& d3,
                                         unsigned a0, unsigned a1, unsigned a2, unsigned a3,
                                         unsigned b0, unsigned b1) {
    asm volatile(
        "mma.sync.aligned.m16n8k8.row.col.f32.tf32.tf32.f32 "
        "{%0,%1,%2,%3}, {%4,%5,%6,%7}, {%8,%9}, {%0,%1,%2,%3};\n"
        : "+f"(d0), "+f"(d1), "+f"(d2), "+f"(d3)
        : "r"(a0), "r"(a1), "r"(a2), "r"(a3), "r"(b0), "r"(b1));
}

__global__ __launch_bounds__(128)
void kron_kernel(const float* __restrict__ x,
                 const float* __restrict__ diag_scale,
                 float* __restrict__ out, int ntiles) {
    extern __shared__ float smem[];
    float* sDiag = smem;                       // 4096 floats (fp32, applied at load)
    float* sMR   = smem + 4096;                // 64*SSTR (tf32 bits)
    float* sXs   = sMR + 64 * SSTR;            // 64*SSTR (tf32 bits)
    float* sT    = sXs + 64 * SSTR;            // 4 warps * 16*SSTR (tf32 bits)

    int tid  = threadIdx.x;
    int warp = tid >> 5, lane = tid & 31;
    int g = lane >> 2, t4 = lane & 3;
    int strip = warp * 16;                     // this warp's 16 output rows (l)

    // ---- one-time per-CTA init: diag + M_R to smem, M_L^T A-fragments to regs ----
    for (int i = tid; i < 4096; i += 128) {
        sDiag[i] = diag_scale[i];
        int r = i >> 6, c = i & 63;
        sMR[r * SSTR + c] = __uint_as_float(f2tf(g_MR[i]));
    }
    unsigned a1f[8][4];
#pragma unroll
    for (int kk = 0; kk < 8; ++kk) {
        int i0 = kk * 8 + t4;
        a1f[kk][0] = f2tf(g_ML[(strip + g)     * 64 + i0]);
        a1f[kk][1] = f2tf(g_ML[(strip + g + 8) * 64 + i0]);
        a1f[kk][2] = f2tf(g_ML[(strip + g)     * 64 + i0 + 4]);
        a1f[kk][3] = f2tf(g_ML[(strip + g + 8) * 64 + i0 + 4]);
    }
    __syncthreads();
    float* sTw = sT + warp * 16 * SSTR;

    // ---- software pipeline: prefetch first tile's x into registers ----
    int t = blockIdx.x;
    float4 pf[8];
    if (t < ntiles) {
        const float4* xt = (const float4*)(x + (size_t)t * 4096);
#pragma unroll
        for (int it = 0; it < 8; ++it) pf[it] = xt[it * 128 + tid];
    }

    const float4* dg = (const float4*)sDiag;
    while (t < ntiles) {
        // ---- stage Xs = x_tile * diag_scale into smem (tf32 bits, stride-72 rows) ----
#pragma unroll
        for (int it = 0; it < 8; ++it) {
            int idx = it * 128 + tid;              // float4 index 0..1023
            float4 v = pf[it];
            float4 s = dg[idx];
            uint4 pk = make_uint4(f2tf(v.x * s.x), f2tf(v.y * s.y),
                                  f2tf(v.z * s.z), f2tf(v.w * s.w));
            int row = idx >> 4, col = (idx & 15) << 2;
            *(uint4*)&sXs[row * SSTR + col] = pk;
        }
        __syncthreads();

        // ---- issue next tile's global loads early (overlap with GEMMs) ----
        int tn = t + gridDim.x;
        if (tn < ntiles) {
            const float4* xtn = (const float4*)(x + (size_t)tn * 4096);
#pragma unroll
            for (int it = 0; it < 8; ++it) pf[it] = xtn[it * 128 + tid];
        }

        // ---- GEMM1: T_strip[16 x 64] = (M_L^T)_strip @ Xs  (k = i) ----
#pragma unroll
        for (int nn = 0; nn < 8; ++nn) {
            float c0 = 0.f, c1 = 0.f, c2 = 0.f, c3 = 0.f;
#pragma unroll
            for (int kk = 0; kk < 8; ++kk) {
                unsigned b0 = __float_as_uint(sXs[(kk * 8 + t4)     * SSTR + nn * 8 + g]);
                unsigned b1 = __float_as_uint(sXs[(kk * 8 + t4 + 4) * SSTR + nn * 8 + g]);
                mma_tf32(c0, c1, c2, c3,
                         a1f[kk][0], a1f[kk][1], a1f[kk][2], a1f[kk][3], b0, b1);
            }
            // stage to warp-private strip (tf32 bits), C-layout -> row-major
            *(uint2*)&sTw[g       * SSTR + nn * 8 + 2 * t4] = make_uint2(f2tf(c0), f2tf(c1));
            *(uint2*)&sTw[(g + 8) * SSTR + nn * 8 + 2 * t4] = make_uint2(f2tf(c2), f2tf(c3));
        }
        __syncwarp();   // warp-local: T written by this warp, read only by this warp

        // ---- A2 fragments from T_strip (k = j) ----
        unsigned a2f[8][4];
#pragma unroll
        for (int kk = 0; kk < 8; ++kk) {
            int j0 = kk * 8 + t4;
            a2f[kk][0] = __float_as_uint(sTw[g       * SSTR + j0]);
            a2f[kk][1] = __float_as_uint(sTw[(g + 8) * SSTR + j0]);
            a2f[kk][2] = __float_as_uint(sTw[g       * SSTR + j0 + 4]);
            a2f[kk][3] = __float_as_uint(sTw[(g + 8) * SSTR + j0 + 4]);
        }

        // ---- GEMM2: O_strip = T_strip @ M_R, direct coalesced store ----
        float* ot = out + (size_t)t * 4096;
#pragma unroll
        for (int nn = 0; nn < 8; ++nn) {
            float c0 = 0.f, c1 = 0.f, c2 = 0.f, c3 = 0.f;
#pragma unroll
            for (int kk = 0; kk < 8; ++kk) {
                unsigned b0 = __float_as_uint(sMR[(kk * 8 + t4)     * SSTR + nn * 8 + g]);
                unsigned b1 = __float_as_uint(sMR[(kk * 8 + t4 + 4) * SSTR + nn * 8 + g]);
                mma_tf32(c0, c1, c2, c3,
                         a2f[kk][0], a2f[kk][1], a2f[kk][2], a2f[kk][3], b0, b1);
            }
            int row = strip + g, col = nn * 8 + 2 * t4;
            *(float2*)&ot[row * 64 + col]       = make_float2(c0, c1);
            *(float2*)&ot[(row + 8) * 64 + col] = make_float2(c2, c3);
        }
        __syncthreads();   // all warps done with sXs before next tile overwrites it
        t = tn;
    }
}

// ---------------- launch ----------------
extern "C" void kernel_launch(void* const* d_in, const int* in_sizes, int n_in,
                              void* d_out, int out_size) {
    const float* x          = (const float*)d_in[0];
    const float* u_left     = (const float*)d_in[1];
    const float* v_left     = (const float*)d_in[2];
    const float* diag_left  = (const float*)d_in[3];
    const float* u_right    = (const float*)d_in[4];
    const float* v_right    = (const float*)d_in[5];
    const float* diag_right = (const float*)d_in[6];
    const float* diag_scale = (const float*)d_in[7];
    float* out = (float*)d_out;

    int ntiles = in_sizes[0] / 4096;

    const int CAYLEY_SMEM  = 4 * 64 * MSTR * (int)sizeof(float);  // 69632
    const int COMPOSE_SMEM = 3 * 64 * MSTR * (int)sizeof(float);  // 52224
    const int KRON_SMEM    = (4096 + 3 * 64 * SSTR) * (int)sizeof(float);  // 71680
    cudaFuncSetAttribute(cayley_kernel,  cudaFuncAttributeMaxDynamicSharedMemorySize, CAYLEY_SMEM);
    cudaFuncSetAttribute(compose_kernel, cudaFuncAttributeMaxDynamicSharedMemorySize, COMPOSE_SMEM);
    cudaFuncSetAttribute(kron_kernel,    cudaFuncAttributeMaxDynamicSharedMemorySize, KRON_SMEM);

    cayley_kernel<<<4, 256, CAYLEY_SMEM>>>(u_left, v_left, u_right, v_right);
    compose_kernel<<<2, 256, COMPOSE_SMEM>>>(diag_left, diag_right);

    int grid = ntiles < 456 ? (ntiles > 0 ? ntiles : 1) : 456;  // 152 SMs * 3
    kron_kernel<<<grid, 128, KRON_SMEM>>>(x, diag_scale, out, ntiles);
}

// round 4
// speedup vs baseline: 2.0567x; 1.0449x over previous
#include <cuda_runtime.h>
#include <cstdint>

// ============================================================
// SVDDecomposeTransMatrix:
//   m_left  = Cayley(u_left)  @ diag(diag_left)  @ Cayley(v_left)    [64x64]
//   m_right = Cayley(u_right) @ diag(diag_right) @ Cayley(v_right)   [64x64]
//   xs = x * diag_scale ; per 64x64 tile: out = m_left^T @ Xs @ m_right
//
// Cayley via truncated geometric series with doubling (||A/2|| ~ 0.16):
//   (I-B)^{-1}(I+B):  S=I+B; S+=B^2 S; S+=B^4 S; S+=B^8 S; Q=S+B S   (k<16, err ~1e-13)
// ============================================================

__device__ float g_Q[4][64 * 64];
__device__ float g_ML[64 * 64];   // TRANSPOSED m_left: g_ML[l*64+i] = m_left[i][l]
__device__ float g_MR[64 * 64];   // m_right, row-major

#define MSTR 68   // smem row stride (floats) for prep matmuls

// C = A*B (+ Sadd), 64x64, stride MSTR, 512 threads, 2x4 register tiles.
template <bool FUSED_ADD>
__device__ __forceinline__ void mm64_512(const float* __restrict__ A,
                                         const float* __restrict__ B,
                                         const float* __restrict__ Sadd,
                                         float* __restrict__ C, int tid) {
    int c0 = (tid & 15) * 4;
    int r0 = (tid >> 4) * 2;
    float a00=0,a01=0,a02=0,a03=0, a10=0,a11=0,a12=0,a13=0;
#pragma unroll 8
    for (int k = 0; k < 64; ++k) {
        float4 b = *(const float4*)&B[k * MSTR + c0];
        float x0 = A[(r0 + 0) * MSTR + k];
        float x1 = A[(r0 + 1) * MSTR + k];
        a00 += x0*b.x; a01 += x0*b.y; a02 += x0*b.z; a03 += x0*b.w;
        a10 += x1*b.x; a11 += x1*b.y; a12 += x1*b.z; a13 += x1*b.w;
    }
    if (FUSED_ADD) {
        float4 s0 = *(const float4*)&Sadd[(r0 + 0) * MSTR + c0];
        float4 s1 = *(const float4*)&Sadd[(r0 + 1) * MSTR + c0];
        a00 += s0.x; a01 += s0.y; a02 += s0.z; a03 += s0.w;
        a10 += s1.x; a11 += s1.y; a12 += s1.z; a13 += s1.w;
    }
    *(float4*)&C[(r0 + 0) * MSTR + c0] = make_float4(a00, a01, a02, a03);
    *(float4*)&C[(r0 + 1) * MSTR + c0] = make_float4(a10, a11, a12, a13);
}

// ---------------- Prep 1: 4 Cayley transforms (one per block, 512 thr) ----------------
__global__ __launch_bounds__(512)
void cayley_kernel(const float* __restrict__ u_left,
                   const float* __restrict__ v_left,
                   const float* __restrict__ u_right,
                   const float* __restrict__ v_right) {
    extern __shared__ float sm[];
    float* sB = sm;                    // B = A/2
    float* s0 = sB + 64 * MSTR;
    float* s1 = s0 + 64 * MSTR;
    float* p0 = s1 + 64 * MSTR;
    float* p1 = p0 + 64 * MSTR;

    const float* X = (blockIdx.x == 0) ? u_left :
                     (blockIdx.x == 1) ? v_left :
                     (blockIdx.x == 2) ? u_right : v_right;
    int tid = threadIdx.x;

    for (int idx = tid; idx < 4096; idx += 512) {
        int i = idx >> 6, j = idx & 63;
        float a = (i > j) ? X[i * 64 + j] : (i < j ? -X[j * 64 + i] : 0.f);
        float b = 0.5f * a;
        sB[i * MSTR + j] = b;
        s0[i * MSTR + j] = (i == j) ? 1.f + b : b;   // S = I + B  (k<2)
    }
    __syncthreads();

    mm64_512<false>(sB, sB, nullptr, p0, tid); __syncthreads();  // p0 = B^2
    mm64_512<true >(p0, s0, s0, s1, tid);      __syncthreads();  // s1 = S(k<4)
    mm64_512<false>(p0, p0, nullptr, p1, tid); __syncthreads();  // p1 = B^4
    mm64_512<true >(p1, s1, s1, s0, tid);      __syncthreads();  // s0 = S(k<8)
    mm64_512<false>(p1, p1, nullptr, p0, tid); __syncthreads();  // p0 = B^8
    mm64_512<true >(p0, s0, s0, s1, tid);      __syncthreads();  // s1 = S(k<16)
    mm64_512<true >(sB, s1, s1, s0, tid);      __syncthreads();  // s0 = Q = (I+B)S

    float* dst = g_Q[blockIdx.x];
    for (int idx = tid; idx < 4096; idx += 512) {
        int i = idx >> 6, j = idx & 63;
        dst[idx] = s0[i * MSTR + j];
    }
}

// ---------------- Prep 2: compose M = Qa @ diag(d) @ Qb (2 blocks, 512 thr) ----------------
__global__ __launch_bounds__(512)
void compose_kernel(const float* __restrict__ diag_left,
                    const float* __restrict__ diag_right) {
    extern __shared__ float sm[];
    float* sA = sm;                   // Qa
    float* sD = sA + 64 * MSTR;       // d[c] * Qb[c][b]
    float* sC = sD + 64 * MSTR;
    int tid = threadIdx.x;
    const float* Qa = g_Q[blockIdx.x * 2];
    const float* Qb = g_Q[blockIdx.x * 2 + 1];
    const float* d  = blockIdx.x ? diag_right : diag_left;

    for (int idx = tid; idx < 4096; idx += 512) {
        int i = idx >> 6, j = idx & 63;
        sA[i * MSTR + j] = Qa[idx];
        sD[i * MSTR + j] = d[i] * Qb[idx];
    }
    __syncthreads();
    mm64_512<false>(sA, sD, nullptr, sC, tid);
    __syncthreads();
    for (int idx = tid; idx < 4096; idx += 512) {
        int a = idx >> 6, b = idx & 63;
        float v = sC[a * MSTR + b];
        if (blockIdx.x == 0) g_ML[b * 64 + a] = v;   // store m_left TRANSPOSED
        else                 g_MR[a * 64 + b] = v;
    }
}

// ---------------- Main: persistent batched 64x64x64x2 GEMM, TF32 mma ----------------
#define SSTR 72   // smem row stride in floats (conflict-free B-fragment reads)

__device__ __forceinline__ unsigned f2tf(float f) {
    unsigned u;
    asm("cvt.rna.tf32.f32 %0, %1;" : "=r"(u) : "f"(f));
    return u;
}

__device__ __forceinline__ void mma_tf32(float& d0, float& d1, float& d2, float& d3,
                                         unsigned a0, unsigned a1, unsigned a2, unsigned a3,
                                         unsigned b0, unsigned b1) {
    asm volatile(
        "mma.sync.aligned.m16n8k8.row.col.f32.tf32.tf32.f32 "
        "{%0,%1,%2,%3}, {%4,%5,%6,%7}, {%8,%9}, {%0,%1,%2,%3};\n"
        : "+f"(d0), "+f"(d1), "+f"(d2), "+f"(d3)
        : "r"(a0), "r"(a1), "r"(a2), "r"(a3), "r"(b0), "r"(b1));
}

__global__ __launch_bounds__(128, 4)
void kron_kernel(const float* __restrict__ x,
                 const float* __restrict__ diag_scale,
                 float* __restrict__ out, int ntiles) {
    extern __shared__ float smem[];
    float* sDiag = smem;                       // 4096 floats (fp32, applied at load)
    float* sMR   = smem + 4096;                // 64*SSTR (tf32 bits)
    float* sXs   = sMR + 64 * SSTR;            // 64*SSTR (tf32 bits); T stored in-place

    int tid  = threadIdx.x;
    int warp = tid >> 5, lane = tid & 31;
    int g = lane >> 2, t4 = lane & 3;
    int strip = warp * 16;                     // this warp's 16 output rows (l)

    // ---- one-time per-CTA init: diag + M_R to smem, M_L^T A-fragments to regs ----
    for (int i = tid; i < 4096; i += 128) {
        sDiag[i] = diag_scale[i];
        int r = i >> 6, c = i & 63;
        sMR[r * SSTR + c] = __uint_as_float(f2tf(g_MR[i]));
    }
    unsigned a1f[8][4];
#pragma unroll
    for (int kk = 0; kk < 8; ++kk) {
        int i0 = kk * 8 + t4;
        a1f[kk][0] = f2tf(g_ML[(strip + g)     * 64 + i0]);
        a1f[kk][1] = f2tf(g_ML[(strip + g + 8) * 64 + i0]);
        a1f[kk][2] = f2tf(g_ML[(strip + g)     * 64 + i0 + 4]);
        a1f[kk][3] = f2tf(g_ML[(strip + g + 8) * 64 + i0 + 4]);
    }
    __syncthreads();

    // ---- software pipeline: prefetch first tile's x into registers ----
    int t = blockIdx.x;
    float4 pf[8];
    if (t < ntiles) {
        const float4* xt = (const float4*)(x + (size_t)t * 4096);
#pragma unroll
        for (int it = 0; it < 8; ++it) pf[it] = xt[it * 128 + tid];
    }

    const float4* dg = (const float4*)sDiag;
    while (t < ntiles) {
        // ---- stage Xs = x_tile * diag_scale into smem (tf32 bits) ----
#pragma unroll
        for (int it = 0; it < 8; ++it) {
            int idx = it * 128 + tid;              // float4 index 0..1023
            float4 v = pf[it];
            float4 s = dg[idx];
            uint4 pk = make_uint4(f2tf(v.x * s.x), f2tf(v.y * s.y),
                                  f2tf(v.z * s.z), f2tf(v.w * s.w));
            int row = idx >> 4, col = (idx & 15) << 2;
            *(uint4*)&sXs[row * SSTR + col] = pk;
        }
        __syncthreads();

        // ---- issue next tile's global loads early (overlap with GEMMs) ----
        int tn = t + gridDim.x;
        if (tn < ntiles) {
            const float4* xtn = (const float4*)(x + (size_t)tn * 4096);
#pragma unroll
            for (int it = 0; it < 8; ++it) pf[it] = xtn[it * 128 + tid];
        }

        // ---- GEMM1: T_strip[16 x 64] = (M_L^T)_strip @ Xs, all in regs ----
        float c1[8][4];
#pragma unroll
        for (int nn = 0; nn < 8; ++nn) {
            c1[nn][0] = 0.f; c1[nn][1] = 0.f; c1[nn][2] = 0.f; c1[nn][3] = 0.f;
#pragma unroll
            for (int kk = 0; kk < 8; ++kk) {
                unsigned b0 = __float_as_uint(sXs[(kk * 8 + t4)     * SSTR + nn * 8 + g]);
                unsigned b1 = __float_as_uint(sXs[(kk * 8 + t4 + 4) * SSTR + nn * 8 + g]);
                mma_tf32(c1[nn][0], c1[nn][1], c1[nn][2], c1[nn][3],
                         a1f[kk][0], a1f[kk][1], a1f[kk][2], a1f[kk][3], b0, b1);
            }
        }
        __syncthreads();   // everyone done reading Xs -> safe to overwrite with T

        // ---- write T strip IN-PLACE into sXs rows [strip, strip+16) ----
#pragma unroll
        for (int nn = 0; nn < 8; ++nn) {
            *(uint2*)&sXs[(strip + g)     * SSTR + nn * 8 + 2 * t4] =
                make_uint2(f2tf(c1[nn][0]), f2tf(c1[nn][1]));
            *(uint2*)&sXs[(strip + g + 8) * SSTR + nn * 8 + 2 * t4] =
                make_uint2(f2tf(c1[nn][2]), f2tf(c1[nn][3]));
        }
        __syncwarp();   // warp-local: strip written by this warp, read only by this warp

        // ---- A2 fragments from T strip (k = j) ----
        unsigned a2f[8][4];
#pragma unroll
        for (int kk = 0; kk < 8; ++kk) {
            int j0 = kk * 8 + t4;
            a2f[kk][0] = __float_as_uint(sXs[(strip + g)     * SSTR + j0]);
            a2f[kk][1] = __float_as_uint(sXs[(strip + g + 8) * SSTR + j0]);
            a2f[kk][2] = __float_as_uint(sXs[(strip + g)     * SSTR + j0 + 4]);
            a2f[kk][3] = __float_as_uint(sXs[(strip + g + 8) * SSTR + j0 + 4]);
        }

        // ---- GEMM2: O_strip = T_strip @ M_R, direct coalesced store ----
        float* ot = out + (size_t)t * 4096;
#pragma unroll
        for (int nn = 0; nn < 8; ++nn) {
            float c0 = 0.f, c1v = 0.f, c2 = 0.f, c3 = 0.f;
#pragma unroll
            for (int kk = 0; kk < 8; ++kk) {
                unsigned b0 = __float_as_uint(sMR[(kk * 8 + t4)     * SSTR + nn * 8 + g]);
                unsigned b1 = __float_as_uint(sMR[(kk * 8 + t4 + 4) * SSTR + nn * 8 + g]);
                mma_tf32(c0, c1v, c2, c3,
                         a2f[kk][0], a2f[kk][1], a2f[kk][2], a2f[kk][3], b0, b1);
            }
            int row = strip + g, col = nn * 8 + 2 * t4;
            *(float2*)&ot[row * 64 + col]       = make_float2(c0, c1v);
            *(float2*)&ot[(row + 8) * 64 + col] = make_float2(c2, c3);
        }
        __syncthreads();   // a2f consumed; next staging may overwrite sXs
        t = tn;
    }
}

// ---------------- launch ----------------
extern "C" void kernel_launch(void* const* d_in, const int* in_sizes, int n_in,
                              void* d_out, int out_size) {
    const float* x          = (const float*)d_in[0];
    const float* u_left     = (const float*)d_in[1];
    const float* v_left     = (const float*)d_in[2];
    const float* diag_left  = (const float*)d_in[3];
    const float* u_right    = (const float*)d_in[4];
    const float* v_right    = (const float*)d_in[5];
    const float* diag_right = (const float*)d_in[6];
    const float* diag_scale = (const float*)d_in[7];
    float* out = (float*)d_out;

    int ntiles = in_sizes[0] / 4096;

    const int CAYLEY_SMEM  = 5 * 64 * MSTR * (int)sizeof(float);  // 87040
    const int COMPOSE_SMEM = 3 * 64 * MSTR * (int)sizeof(float);  // 52224
    const int KRON_SMEM    = (4096 + 2 * 64 * SSTR) * (int)sizeof(float);  // 53248
    cudaFuncSetAttribute(cayley_kernel,  cudaFuncAttributeMaxDynamicSharedMemorySize, CAYLEY_SMEM);
    cudaFuncSetAttribute(compose_kernel, cudaFuncAttributeMaxDynamicSharedMemorySize, COMPOSE_SMEM);
    cudaFuncSetAttribute(kron_kernel,    cudaFuncAttributeMaxDynamicSharedMemorySize, KRON_SMEM);

    cayley_kernel<<<4, 512, CAYLEY_SMEM>>>(u_left, v_left, u_right, v_right);
    compose_kernel<<<2, 512, COMPOSE_SMEM>>>(diag_left, diag_right);

    int grid = ntiles < 608 ? (ntiles > 0 ? ntiles : 1) : 608;  // 152 SMs * 4
    kron_kernel<<<grid, 128, KRON_SMEM>>>(x, diag_scale, out, ntiles);
}